// round 6
// baseline (speedup 1.0000x reference)
#include <cuda_runtime.h>
#include <cstdint>
#include <cstdio>

// ---------------------------------------------------------------------------
// MegrezMoeMoE: T=1024 tokens, H=2048, E=32 experts, I=1024, TOPK=6,
// NGROUP=8, TOPKG=4, shared expert I=1024, SCALE=2.5
// ---------------------------------------------------------------------------

constexpr int TTOK  = 1024;
constexpr int HDIM  = 2048;
constexpr int EXP   = 32;
constexpr int IDIM  = 1024;
constexpr int TOPK  = 6;
constexpr int NGRP  = 8;
constexpr int TOPKG = 4;
constexpr int GSIZE = EXP / NGRP;      // 4
constexpr int PAIRS = TTOK * TOPK;     // 6144
constexpr float RSCALE = 2.5f;

// ------------------------- scratch (device globals) ------------------------
__device__ int   g_topk_id[PAIRS];
__device__ float g_topk_w[PAIRS];
__device__ int   g_counts[EXP];
__device__ int   g_offsets[EXP];
__device__ int   g_sorted_token[PAIRS];
__device__ float g_sorted_ws[PAIRS];        // topk weight * RSCALE
__device__ int   g_pos_of_pair[PAIRS];
__device__ float g_gu   [(size_t)PAIRS * 2 * IDIM];  // 48MB
__device__ float g_act  [(size_t)PAIRS * IDIM];      // 24MB
__device__ float g_y    [(size_t)PAIRS * HDIM];      // 48MB
__device__ float g_gu_s [(size_t)TTOK * 2 * IDIM];   // 8MB
__device__ float g_act_s[(size_t)TTOK * IDIM];       // 4MB

// ------------------------------ router -------------------------------------
__global__ void router_kernel(const float* __restrict__ hidden,
                              const float* __restrict__ gate_w,
                              const float* __restrict__ e_bias)
{
    int t = blockIdx.x;
    int lane = threadIdx.x;            // 32 threads, lane == expert
    const float* x = hidden + (size_t)t * HDIM;

    float logit = 0.f;
    #pragma unroll 8
    for (int h = 0; h < HDIM; ++h)
        logit += x[h] * gate_w[(size_t)h * EXP + lane];

    float s  = 1.f / (1.f + expf(-logit));
    float sc = s + e_bias[lane];

    __shared__ float sm_s[EXP];
    __shared__ float sm_sc[EXP];
    sm_s[lane]  = s;
    sm_sc[lane] = sc;
    __syncwarp();

    if (lane == 0) {
        float gs[NGRP];
        #pragma unroll
        for (int g = 0; g < NGRP; ++g) {
            float m1 = -1e30f, m2 = -1e30f;
            #pragma unroll
            for (int j = 0; j < GSIZE; ++j) {
                float v = sm_sc[g * GSIZE + j];
                if (v > m1) { m2 = m1; m1 = v; }
                else if (v > m2) { m2 = v; }
            }
            gs[g] = m1 + m2;
        }
        bool gsel[NGRP];
        #pragma unroll
        for (int g = 0; g < NGRP; ++g) gsel[g] = false;
        for (int it = 0; it < TOPKG; ++it) {
            int best = -1; float bv = -1e30f;
            for (int g = 0; g < NGRP; ++g)
                if (!gsel[g] && gs[g] > bv) { bv = gs[g]; best = g; }
            gsel[best] = true;
        }
        bool taken[EXP];
        #pragma unroll
        for (int e = 0; e < EXP; ++e) taken[e] = false;
        int ids[TOPK]; float ws[TOPK]; float wsum = 0.f;
        for (int it = 0; it < TOPK; ++it) {
            int best = -1; float bv = -1e30f;
            for (int e = 0; e < EXP; ++e) {
                if (!gsel[e >> 2] || taken[e]) continue;
                if (sm_sc[e] > bv) { bv = sm_sc[e]; best = e; }
            }
            taken[best] = true;
            ids[it] = best;
            ws[it]  = sm_s[best];
            wsum += ws[it];
        }
        float inv = 1.f / wsum;
        #pragma unroll
        for (int k = 0; k < TOPK; ++k) {
            g_topk_id[t * TOPK + k] = ids[k];
            g_topk_w [t * TOPK + k] = ws[k] * inv;
        }
    }
}

// ---------------------- deterministic counting sort -------------------------
__global__ void count_kernel()
{
    int e = blockIdx.x;
    int tid = threadIdx.x;
    int c = 0;
    for (int p = tid; p < PAIRS; p += blockDim.x)
        c += (g_topk_id[p] == e);
    __shared__ int red[256];
    red[tid] = c;
    __syncthreads();
    for (int s = 128; s > 0; s >>= 1) {
        if (tid < s) red[tid] += red[tid + s];
        __syncthreads();
    }
    if (tid == 0) g_counts[e] = red[0];
}

__global__ void scan_kernel()
{
    if (threadIdx.x == 0) {
        int acc = 0;
        for (int e = 0; e < EXP; ++e) { g_offsets[e] = acc; acc += g_counts[e]; }
    }
}

__global__ void place_kernel()
{
    int e = blockIdx.x;
    int tid = threadIdx.x;
    constexpr int CH = PAIRS / 256;    // 24
    int p0 = tid * CH;
    int c = 0;
    for (int i = 0; i < CH; ++i)
        c += (g_topk_id[p0 + i] == e);

    __shared__ int sc[256];
    sc[tid] = c;
    __syncthreads();
    for (int d = 1; d < 256; d <<= 1) {
        int v = (tid >= d) ? sc[tid - d] : 0;
        __syncthreads();
        sc[tid] += v;
        __syncthreads();
    }
    int pos = g_offsets[e] + sc[tid] - c;
    for (int i = 0; i < CH; ++i) {
        int p = p0 + i;
        if (g_topk_id[p] == e) {
            g_sorted_token[pos] = p / TOPK;
            g_sorted_ws[pos]    = g_topk_w[p] * RSCALE;
            g_pos_of_pair[p]    = pos;
            ++pos;
        }
    }
}

// --------------------------- tf32 GEMM core ---------------------------------
__device__ __forceinline__ uint32_t f2tf(float x)
{
    uint32_t r;
    asm("cvt.rna.tf32.f32 %0, %1;" : "=r"(r) : "f"(x));
    return r;
}

__device__ __forceinline__ void cp_async16(uint32_t dst, const void* src,
                                           int src_bytes)
{
    asm volatile("cp.async.cg.shared.global [%0], [%1], 16, %2;\n"
                 :: "r"(dst), "l"(src), "r"(src_bytes));
}
__device__ __forceinline__ void cp_commit()
{
    asm volatile("cp.async.commit_group;\n");
}
template <int N>
__device__ __forceinline__ void cp_wait()
{
    asm volatile("cp.async.wait_group %0;\n" :: "n"(N));
}

#define MMA_TF32(d, a, b)                                                  \
    asm volatile(                                                          \
        "mma.sync.aligned.m16n8k8.row.col.f32.tf32.tf32.f32 "              \
        "{%0,%1,%2,%3}, {%4,%5,%6,%7}, {%8,%9}, {%0,%1,%2,%3};\n"          \
        : "+f"(d[0]), "+f"(d[1]), "+f"(d[2]), "+f"(d[3])                   \
        : "r"(a[0]), "r"(a[1]), "r"(a[2]), "r"(a[3]), "r"(b[0]), "r"(b[1]))

// BM=64, BN=256, BK=16, 256 threads, 8 warps (2m x 4n), warp tile 32x64.
// 5-stage cp.async pipeline, dynamic smem, 2 CTAs/SM -> 16 warps/SM.
// fp32 staged in smem, cvt.rna.tf32 at fragment load (identical numerics).
constexpr int STAGES = 5;
constexpr int BN = 256;
constexpr int A_FLOATS = 64 * 20;              // [m][k] stride 20
constexpr int B_FLOATS = 16 * 264;             // [k][n] stride 264
constexpr int STAGE_FLOATS = A_FLOATS + B_FLOATS;   // 5504
constexpr int GEMM_SMEM_BYTES = STAGES * STAGE_FLOATS * 4;  // 110080

__global__ __launch_bounds__(256, 2)
void gemm_tf32_kernel(const float* __restrict__ A,
                      const float* __restrict__ Bb,
                      float* __restrict__ C,
                      int M, int N, int K,
                      const int* __restrict__ counts,
                      const int* __restrict__ offsets,
                      const int* __restrict__ rowmap,
                      const float* __restrict__ rowscale,
                      size_t strideB)
{
    extern __shared__ float smem[];

    const int e = blockIdx.z;
    const int m_count = counts ? counts[e] : M;
    const int m0 = blockIdx.x * 64;
    if (m0 >= m_count) return;
    const int base = offsets ? offsets[e] : 0;
    const int n0 = blockIdx.y * BN;
    const float* B = Bb + (size_t)e * strideB;

    const int tid = threadIdx.x;

    // A loader: thread owns row ar, k-quad akq (one 16B cp.async per stage)
    const int ar  = tid >> 2;           // 0..63
    const int akq = tid & 3;            // 0..3
    const bool avalid = (m0 + ar) < m_count;
    const int grow_a = base + m0 + ar;
    const int arow = avalid ? (rowmap ? rowmap[grow_a] : grow_a) : 0;
    const float* Ap = A + (size_t)arow * K + akq * 4;
    const int abytes = avalid ? 16 : 0;

    // B loader: thread owns k-rows bkr+{0,4,8,12}, n-quad bnq (4 cp.async)
    const int bkr = tid >> 6;           // 0..3
    const int bnq = tid & 63;           // 0..63
    const float* Bp = B + (size_t)bkr * N + n0 + bnq * 4;

    const int wid = tid >> 5, lane = tid & 31;
    const int wm = (wid >> 2) * 32, wn = (wid & 3) * 64;
    const int gid = lane >> 2, tig = lane & 3;

    float acc[2][8][4];
    #pragma unroll
    for (int i = 0; i < 2; ++i)
        #pragma unroll
        for (int j = 0; j < 8; ++j)
            #pragma unroll
            for (int k = 0; k < 4; ++k) acc[i][j][k] = 0.f;

    const int nk = K / 16;

    uint32_t a_dst[STAGES];
    uint32_t b_dst[STAGES][4];
    #pragma unroll
    for (int s = 0; s < STAGES; ++s) {
        float* st = smem + s * STAGE_FLOATS;
        a_dst[s] = (uint32_t)__cvta_generic_to_shared(st + ar * 20 + akq * 4);
        #pragma unroll
        for (int r = 0; r < 4; ++r)
            b_dst[s][r] = (uint32_t)__cvta_generic_to_shared(
                st + A_FLOATS + (bkr + r * 4) * 264 + bnq * 4);
    }

    // prologue: stages 0..STAGES-2 in flight
    #pragma unroll
    for (int s = 0; s < STAGES - 1; ++s) {
        if (s < nk) {
            const size_t ko = (size_t)s * 16;
            cp_async16(a_dst[s], Ap + ko, abytes);
            #pragma unroll
            for (int r = 0; r < 4; ++r)
                cp_async16(b_dst[s][r], Bp + ko * N + (size_t)(r * 4) * N, 16);
        }
        cp_commit();
    }

    for (int kt = 0; kt < nk; ++kt) {
        const int buf = kt % STAGES;
        cp_wait<STAGES - 2>();   // stage kt arrived; 3 more in flight
        __syncthreads();

        // issue stage kt+STAGES-1 into the freed buffer
        const int kf = kt + STAGES - 1;
        if (kf < nk) {
            const int fb = kf % STAGES;
            const size_t ko = (size_t)kf * 16;
            cp_async16(a_dst[fb], Ap + ko, abytes);
            #pragma unroll
            for (int r = 0; r < 4; ++r)
                cp_async16(b_dst[fb][r], Bp + ko * N + (size_t)(r * 4) * N, 16);
        }
        cp_commit();

        const float* As = smem + buf * STAGE_FLOATS;          // [m][k] s20
        const float* Bs = As + A_FLOATS;                       // [k][n] s264

        // compute on buf (cvt.rna.tf32 applied at fragment load)
        #pragma unroll
        for (int ks = 0; ks < 2; ++ks) {
            const int kb = ks * 8;
            uint32_t a[2][4], b[8][2];
            #pragma unroll
            for (int mf = 0; mf < 2; ++mf) {
                const int mr = wm + mf * 16 + gid;
                a[mf][0] = f2tf(As[(mr    ) * 20 + kb + tig]);
                a[mf][1] = f2tf(As[(mr + 8) * 20 + kb + tig]);
                a[mf][2] = f2tf(As[(mr    ) * 20 + kb + tig + 4]);
                a[mf][3] = f2tf(As[(mr + 8) * 20 + kb + tig + 4]);
            }
            #pragma unroll
            for (int nf = 0; nf < 8; ++nf) {
                const int nc = wn + nf * 8 + gid;
                b[nf][0] = f2tf(Bs[(kb + tig    ) * 264 + nc]);
                b[nf][1] = f2tf(Bs[(kb + tig + 4) * 264 + nc]);
            }
            #pragma unroll
            for (int mf = 0; mf < 2; ++mf)
                #pragma unroll
                for (int nf = 0; nf < 8; ++nf)
                    MMA_TF32(acc[mf][nf], a[mf], b[nf]);
        }
    }

    // epilogue
    #pragma unroll
    for (int mf = 0; mf < 2; ++mf) {
        #pragma unroll
        for (int half = 0; half < 2; ++half) {
            const int rloc = wm + mf * 16 + gid + half * 8;
            if (m0 + rloc < m_count) {
                const int grow = base + m0 + rloc;
                const float scl = rowscale ? rowscale[grow] : 1.f;
                float* crow = C + (size_t)grow * N + n0 + wn;
                #pragma unroll
                for (int nf = 0; nf < 8; ++nf) {
                    float2 v;
                    v.x = acc[mf][nf][half * 2 + 0] * scl;
                    v.y = acc[mf][nf][half * 2 + 1] * scl;
                    *(float2*)(crow + nf * 8 + tig * 2) = v;
                }
            }
        }
    }
}

// --------------------------- silu * mul -------------------------------------
__global__ void silu_mul_kernel(const float* __restrict__ gu,
                                float* __restrict__ act, int rows)
{
    const int QI = IDIM / 4;
    int total = rows * QI;
    for (int idx = blockIdx.x * blockDim.x + threadIdx.x; idx < total;
         idx += gridDim.x * blockDim.x) {
        int r = idx / QI;
        int q = idx - r * QI;
        const float* row = gu + (size_t)r * 2 * IDIM;
        float4 g = *(const float4*)(row + q * 4);
        float4 u = *(const float4*)(row + IDIM + q * 4);
        float4 o;
        o.x = g.x / (1.f + __expf(-g.x)) * u.x;
        o.y = g.y / (1.f + __expf(-g.y)) * u.y;
        o.z = g.z / (1.f + __expf(-g.z)) * u.z;
        o.w = g.w / (1.f + __expf(-g.w)) * u.w;
        *(float4*)(act + (size_t)r * IDIM + q * 4) = o;
    }
}

// --------------------------- combine ----------------------------------------
__global__ void combine_kernel(float* __restrict__ out)
{
    const int t = blockIdx.x;
    int pos[TOPK];
    #pragma unroll
    for (int k = 0; k < TOPK; ++k) pos[k] = g_pos_of_pair[t * TOPK + k];
    for (int q = threadIdx.x; q < HDIM / 4; q += blockDim.x) {
        float4 o = *(float4*)(out + (size_t)t * HDIM + q * 4);
        #pragma unroll
        for (int k = 0; k < TOPK; ++k) {
            float4 v = *(const float4*)(g_y + (size_t)pos[k] * HDIM + q * 4);
            o.x += v.x; o.y += v.y; o.z += v.z; o.w += v.w;
        }
        *(float4*)(out + (size_t)t * HDIM + q * 4) = o;
    }
}

// --------------------------- launch -----------------------------------------
extern "C" void kernel_launch(void* const* d_in, const int* in_sizes, int n_in,
                              void* d_out, int out_size)
{
    const float* hidden    = (const float*)d_in[0];
    const float* gate_w    = (const float*)d_in[1];
    const float* e_bias    = (const float*)d_in[2];
    const float* w_gate_up = (const float*)d_in[3];
    const float* w_down    = (const float*)d_in[4];
    const float* sh_gu     = (const float*)d_in[5];
    const float* sh_down   = (const float*)d_in[6];
    float* out             = (float*)d_out;

    void *p_gu, *p_act, *p_y, *p_gu_s, *p_act_s, *p_counts, *p_offsets,
         *p_stok, *p_sws;
    cudaGetSymbolAddress(&p_gu,     g_gu);
    cudaGetSymbolAddress(&p_act,    g_act);
    cudaGetSymbolAddress(&p_y,      g_y);
    cudaGetSymbolAddress(&p_gu_s,   g_gu_s);
    cudaGetSymbolAddress(&p_act_s,  g_act_s);
    cudaGetSymbolAddress(&p_counts, g_counts);
    cudaGetSymbolAddress(&p_offsets,g_offsets);
    cudaGetSymbolAddress(&p_stok,   g_sorted_token);
    cudaGetSymbolAddress(&p_sws,    g_sorted_ws);

    static bool attr_set = false;
    if (!attr_set) {
        cudaFuncSetAttribute(gemm_tf32_kernel,
                             cudaFuncAttributeMaxDynamicSharedMemorySize,
                             GEMM_SMEM_BYTES);
        attr_set = true;
    }

    // launch 0-2: router, count, scan
    router_kernel<<<TTOK, 32>>>(hidden, gate_w, e_bias);
    count_kernel<<<EXP, 256>>>();
    scan_kernel<<<1, 32>>>();

    // launch 3 (ncu profiles this): shared expert gate_up GEMM
    gemm_tf32_kernel<<<dim3(16, 2 * IDIM / BN, 1), 256, GEMM_SMEM_BYTES>>>(
        hidden, sh_gu, (float*)p_gu_s,
        TTOK, 2 * IDIM, HDIM,
        nullptr, nullptr, nullptr, nullptr, 0);

    // launch 4: place (completes the pair sort)
    place_kernel<<<EXP, 256>>>();

    // routed gate_up -> g_gu [6144, 2048]
    gemm_tf32_kernel<<<dim3(16, 2 * IDIM / BN, EXP), 256, GEMM_SMEM_BYTES>>>(
        hidden, w_gate_up, (float*)p_gu,
        0, 2 * IDIM, HDIM,
        (const int*)p_counts, (const int*)p_offsets, (const int*)p_stok,
        nullptr, (size_t)HDIM * 2 * IDIM);

    // routed silu*mul -> g_act
    silu_mul_kernel<<<6144, 256>>>((const float*)p_gu, (float*)p_act, PAIRS);

    // routed down, row-scaled by w*2.5 -> g_y
    gemm_tf32_kernel<<<dim3(16, HDIM / BN, EXP), 256, GEMM_SMEM_BYTES>>>(
        (const float*)p_act, w_down, (float*)p_y,
        0, HDIM, IDIM,
        (const int*)p_counts, (const int*)p_offsets, nullptr,
        (const float*)p_sws, (size_t)IDIM * HDIM);

    // shared expert: silu -> down (writes out directly)
    silu_mul_kernel<<<1024, 256>>>((const float*)p_gu_s, (float*)p_act_s, TTOK);
    gemm_tf32_kernel<<<dim3(16, HDIM / BN, 1), 256, GEMM_SMEM_BYTES>>>(
        (const float*)p_act_s, sh_down, out,
        TTOK, HDIM, IDIM,
        nullptr, nullptr, nullptr, nullptr, 0);

    // out += sum of each token's 6 scaled expert rows
    combine_kernel<<<TTOK, 256>>>(out);
}

// round 7
// speedup vs baseline: 1.0744x; 1.0744x over previous
#include <cuda_runtime.h>
#include <cstdint>
#include <cstdio>

// ---------------------------------------------------------------------------
// MegrezMoeMoE: T=1024 tokens, H=2048, E=32 experts, I=1024, TOPK=6,
// NGROUP=8, TOPKG=4, shared expert I=1024, SCALE=2.5
//
// GEMMs feed raw fp32 bit patterns to tf32 mma.sync (hardware truncates the
// mantissa, RZ). The systematic truncation bias (1-eps_a)(1-eps_b),
// eps = 2^-11 * E[1/mantissa] = 2^-11 * 0.7213, is cancelled by multiplying
// every GEMM output by CORR = 1/(1-eps)^2 ~= 1.0007045 in the epilogue,
// BEFORE any nonlinearity. Residual noise is zero-mean with the same
// variance as rna rounding.
// ---------------------------------------------------------------------------

constexpr int TTOK  = 1024;
constexpr int HDIM  = 2048;
constexpr int EXP   = 32;
constexpr int IDIM  = 1024;
constexpr int TOPK  = 6;
constexpr int NGRP  = 8;
constexpr int TOPKG = 4;
constexpr int GSIZE = EXP / NGRP;      // 4
constexpr int PAIRS = TTOK * TOPK;     // 6144
constexpr float RSCALE = 2.5f;
constexpr float CORR  = 1.0007045f;    // tf32-truncation bias correction

// ------------------------- scratch (device globals) ------------------------
__device__ int   g_topk_id[PAIRS];
__device__ float g_topk_w[PAIRS];
__device__ int   g_counts[EXP];
__device__ int   g_offsets[EXP];
__device__ int   g_sorted_token[PAIRS];
__device__ float g_sorted_ws[PAIRS];        // topk weight * RSCALE
__device__ int   g_pos_of_pair[PAIRS];
__device__ float g_gu   [(size_t)PAIRS * 2 * IDIM];  // 48MB
__device__ float g_act  [(size_t)PAIRS * IDIM];      // 24MB
__device__ float g_y    [(size_t)PAIRS * HDIM];      // 48MB
__device__ float g_gu_s [(size_t)TTOK * 2 * IDIM];   // 8MB
__device__ float g_act_s[(size_t)TTOK * IDIM];       // 4MB

// ------------------------------ router -------------------------------------
__global__ void router_kernel(const float* __restrict__ hidden,
                              const float* __restrict__ gate_w,
                              const float* __restrict__ e_bias)
{
    int t = blockIdx.x;
    int lane = threadIdx.x;            // 32 threads, lane == expert
    const float* x = hidden + (size_t)t * HDIM;

    float logit = 0.f;
    #pragma unroll 8
    for (int h = 0; h < HDIM; ++h)
        logit += x[h] * gate_w[(size_t)h * EXP + lane];

    float s  = 1.f / (1.f + expf(-logit));
    float sc = s + e_bias[lane];

    __shared__ float sm_s[EXP];
    __shared__ float sm_sc[EXP];
    sm_s[lane]  = s;
    sm_sc[lane] = sc;
    __syncwarp();

    if (lane == 0) {
        float gs[NGRP];
        #pragma unroll
        for (int g = 0; g < NGRP; ++g) {
            float m1 = -1e30f, m2 = -1e30f;
            #pragma unroll
            for (int j = 0; j < GSIZE; ++j) {
                float v = sm_sc[g * GSIZE + j];
                if (v > m1) { m2 = m1; m1 = v; }
                else if (v > m2) { m2 = v; }
            }
            gs[g] = m1 + m2;
        }
        bool gsel[NGRP];
        #pragma unroll
        for (int g = 0; g < NGRP; ++g) gsel[g] = false;
        for (int it = 0; it < TOPKG; ++it) {
            int best = -1; float bv = -1e30f;
            for (int g = 0; g < NGRP; ++g)
                if (!gsel[g] && gs[g] > bv) { bv = gs[g]; best = g; }
            gsel[best] = true;
        }
        bool taken[EXP];
        #pragma unroll
        for (int e = 0; e < EXP; ++e) taken[e] = false;
        int ids[TOPK]; float ws[TOPK]; float wsum = 0.f;
        for (int it = 0; it < TOPK; ++it) {
            int best = -1; float bv = -1e30f;
            for (int e = 0; e < EXP; ++e) {
                if (!gsel[e >> 2] || taken[e]) continue;
                if (sm_sc[e] > bv) { bv = sm_sc[e]; best = e; }
            }
            taken[best] = true;
            ids[it] = best;
            ws[it]  = sm_s[best];
            wsum += ws[it];
        }
        float inv = 1.f / wsum;
        #pragma unroll
        for (int k = 0; k < TOPK; ++k) {
            g_topk_id[t * TOPK + k] = ids[k];
            g_topk_w [t * TOPK + k] = ws[k] * inv;
        }
    }
}

// ---------------------- deterministic counting sort -------------------------
__global__ void count_kernel()
{
    int e = blockIdx.x;
    int tid = threadIdx.x;
    int c = 0;
    for (int p = tid; p < PAIRS; p += blockDim.x)
        c += (g_topk_id[p] == e);
    __shared__ int red[256];
    red[tid] = c;
    __syncthreads();
    for (int s = 128; s > 0; s >>= 1) {
        if (tid < s) red[tid] += red[tid + s];
        __syncthreads();
    }
    if (tid == 0) g_counts[e] = red[0];
}

__global__ void scan_kernel()
{
    if (threadIdx.x == 0) {
        int acc = 0;
        for (int e = 0; e < EXP; ++e) { g_offsets[e] = acc; acc += g_counts[e]; }
    }
}

__global__ void place_kernel()
{
    int e = blockIdx.x;
    int tid = threadIdx.x;
    constexpr int CH = PAIRS / 256;    // 24
    int p0 = tid * CH;
    int c = 0;
    for (int i = 0; i < CH; ++i)
        c += (g_topk_id[p0 + i] == e);

    __shared__ int sc[256];
    sc[tid] = c;
    __syncthreads();
    for (int d = 1; d < 256; d <<= 1) {
        int v = (tid >= d) ? sc[tid - d] : 0;
        __syncthreads();
        sc[tid] += v;
        __syncthreads();
    }
    int pos = g_offsets[e] + sc[tid] - c;
    for (int i = 0; i < CH; ++i) {
        int p = p0 + i;
        if (g_topk_id[p] == e) {
            g_sorted_token[pos] = p / TOPK;
            g_sorted_ws[pos]    = g_topk_w[p] * RSCALE;
            g_pos_of_pair[p]    = pos;
            ++pos;
        }
    }
}

// --------------------------- tf32 GEMM core ---------------------------------
__device__ __forceinline__ void cp_async16(uint32_t dst, const void* src,
                                           int src_bytes)
{
    asm volatile("cp.async.cg.shared.global [%0], [%1], 16, %2;\n"
                 :: "r"(dst), "l"(src), "r"(src_bytes));
}
__device__ __forceinline__ void cp_commit()
{
    asm volatile("cp.async.commit_group;\n");
}
template <int N>
__device__ __forceinline__ void cp_wait()
{
    asm volatile("cp.async.wait_group %0;\n" :: "n"(N));
}

#define MMA_TF32(d, a, b)                                                  \
    asm volatile(                                                          \
        "mma.sync.aligned.m16n8k8.row.col.f32.tf32.tf32.f32 "              \
        "{%0,%1,%2,%3}, {%4,%5,%6,%7}, {%8,%9}, {%0,%1,%2,%3};\n"          \
        : "+f"(d[0]), "+f"(d[1]), "+f"(d[2]), "+f"(d[3])                   \
        : "r"(a[0]), "r"(a[1]), "r"(a[2]), "r"(a[3]), "r"(b[0]), "r"(b[1]))

// BM=64, BN=256, BK=16, 256 threads, 8 warps (2m x 4n), warp tile 32x64.
// 5-stage cp.async pipeline, dynamic smem.
// Raw fp32 fed to tf32 MMA (RZ truncation); bias corrected via CORR in
// epilogue. No per-fragment CVT instructions.
constexpr int STAGES = 5;
constexpr int BN = 256;
constexpr int A_FLOATS = 64 * 20;              // [m][k] stride 20
constexpr int B_FLOATS = 16 * 264;             // [k][n] stride 264
constexpr int STAGE_FLOATS = A_FLOATS + B_FLOATS;   // 5504
constexpr int GEMM_SMEM_BYTES = STAGES * STAGE_FLOATS * 4;  // 110080

__global__ __launch_bounds__(256, 2)
void gemm_tf32_kernel(const float* __restrict__ A,
                      const float* __restrict__ Bb,
                      float* __restrict__ C,
                      int M, int N, int K,
                      const int* __restrict__ counts,
                      const int* __restrict__ offsets,
                      const int* __restrict__ rowmap,
                      const float* __restrict__ rowscale,
                      size_t strideB)
{
    extern __shared__ float smem[];

    const int e = blockIdx.z;
    const int m_count = counts ? counts[e] : M;
    const int m0 = blockIdx.x * 64;
    if (m0 >= m_count) return;
    const int base = offsets ? offsets[e] : 0;
    const int n0 = blockIdx.y * BN;
    const float* B = Bb + (size_t)e * strideB;

    const int tid = threadIdx.x;

    // A loader: thread owns row ar, k-quad akq (one 16B cp.async per stage)
    const int ar  = tid >> 2;           // 0..63
    const int akq = tid & 3;            // 0..3
    const bool avalid = (m0 + ar) < m_count;
    const int grow_a = base + m0 + ar;
    const int arow = avalid ? (rowmap ? rowmap[grow_a] : grow_a) : 0;
    const float* Ap = A + (size_t)arow * K + akq * 4;
    const int abytes = avalid ? 16 : 0;

    // B loader: thread owns k-rows bkr+{0,4,8,12}, n-quad bnq (4 cp.async)
    const int bkr = tid >> 6;           // 0..3
    const int bnq = tid & 63;           // 0..63
    const float* Bp = B + (size_t)bkr * N + n0 + bnq * 4;

    const int wid = tid >> 5, lane = tid & 31;
    const int wm = (wid >> 2) * 32, wn = (wid & 3) * 64;
    const int gid = lane >> 2, tig = lane & 3;

    float acc[2][8][4];
    #pragma unroll
    for (int i = 0; i < 2; ++i)
        #pragma unroll
        for (int j = 0; j < 8; ++j)
            #pragma unroll
            for (int k = 0; k < 4; ++k) acc[i][j][k] = 0.f;

    const int nk = K / 16;

    uint32_t a_dst[STAGES];
    uint32_t b_dst[STAGES][4];
    #pragma unroll
    for (int s = 0; s < STAGES; ++s) {
        float* st = smem + s * STAGE_FLOATS;
        a_dst[s] = (uint32_t)__cvta_generic_to_shared(st + ar * 20 + akq * 4);
        #pragma unroll
        for (int r = 0; r < 4; ++r)
            b_dst[s][r] = (uint32_t)__cvta_generic_to_shared(
                st + A_FLOATS + (bkr + r * 4) * 264 + bnq * 4);
    }

    // prologue: stages 0..STAGES-2 in flight
    #pragma unroll
    for (int s = 0; s < STAGES - 1; ++s) {
        if (s < nk) {
            const size_t ko = (size_t)s * 16;
            cp_async16(a_dst[s], Ap + ko, abytes);
            #pragma unroll
            for (int r = 0; r < 4; ++r)
                cp_async16(b_dst[s][r], Bp + ko * N + (size_t)(r * 4) * N, 16);
        }
        cp_commit();
    }

    for (int kt = 0; kt < nk; ++kt) {
        const int buf = kt % STAGES;
        cp_wait<STAGES - 2>();   // stage kt arrived; 3 more in flight
        __syncthreads();

        // issue stage kt+STAGES-1 into the freed buffer
        const int kf = kt + STAGES - 1;
        if (kf < nk) {
            const int fb = kf % STAGES;
            const size_t ko = (size_t)kf * 16;
            cp_async16(a_dst[fb], Ap + ko, abytes);
            #pragma unroll
            for (int r = 0; r < 4; ++r)
                cp_async16(b_dst[fb][r], Bp + ko * N + (size_t)(r * 4) * N, 16);
        }
        cp_commit();

        const uint32_t* As = (const uint32_t*)(smem + buf * STAGE_FLOATS);
        const uint32_t* Bs = As + A_FLOATS;

        // compute on buf: raw fp32 bits straight into tf32 MMA (no CVT)
        #pragma unroll
        for (int ks = 0; ks < 2; ++ks) {
            const int kb = ks * 8;
            uint32_t a[2][4], b[8][2];
            #pragma unroll
            for (int mf = 0; mf < 2; ++mf) {
                const int mr = wm + mf * 16 + gid;
                a[mf][0] = As[(mr    ) * 20 + kb + tig];
                a[mf][1] = As[(mr + 8) * 20 + kb + tig];
                a[mf][2] = As[(mr    ) * 20 + kb + tig + 4];
                a[mf][3] = As[(mr + 8) * 20 + kb + tig + 4];
            }
            #pragma unroll
            for (int nf = 0; nf < 8; ++nf) {
                const int nc = wn + nf * 8 + gid;
                b[nf][0] = Bs[(kb + tig    ) * 264 + nc];
                b[nf][1] = Bs[(kb + tig + 4) * 264 + nc];
            }
            #pragma unroll
            for (int mf = 0; mf < 2; ++mf)
                #pragma unroll
                for (int nf = 0; nf < 8; ++nf)
                    MMA_TF32(acc[mf][nf], a[mf], b[nf]);
        }
    }

    // epilogue (CORR cancels tf32-truncation bias; folded with rowscale)
    #pragma unroll
    for (int mf = 0; mf < 2; ++mf) {
        #pragma unroll
        for (int half = 0; half < 2; ++half) {
            const int rloc = wm + mf * 16 + gid + half * 8;
            if (m0 + rloc < m_count) {
                const int grow = base + m0 + rloc;
                const float scl = (rowscale ? rowscale[grow] : 1.f) * CORR;
                float* crow = C + (size_t)grow * N + n0 + wn;
                #pragma unroll
                for (int nf = 0; nf < 8; ++nf) {
                    float2 v;
                    v.x = acc[mf][nf][half * 2 + 0] * scl;
                    v.y = acc[mf][nf][half * 2 + 1] * scl;
                    *(float2*)(crow + nf * 8 + tig * 2) = v;
                }
            }
        }
    }
}

// --------------------------- silu * mul -------------------------------------
__global__ void silu_mul_kernel(const float* __restrict__ gu,
                                float* __restrict__ act, int rows)
{
    const int QI = IDIM / 4;
    int total = rows * QI;
    for (int idx = blockIdx.x * blockDim.x + threadIdx.x; idx < total;
         idx += gridDim.x * blockDim.x) {
        int r = idx / QI;
        int q = idx - r * QI;
        const float* row = gu + (size_t)r * 2 * IDIM;
        float4 g = *(const float4*)(row + q * 4);
        float4 u = *(const float4*)(row + IDIM + q * 4);
        float4 o;
        o.x = g.x / (1.f + __expf(-g.x)) * u.x;
        o.y = g.y / (1.f + __expf(-g.y)) * u.y;
        o.z = g.z / (1.f + __expf(-g.z)) * u.z;
        o.w = g.w / (1.f + __expf(-g.w)) * u.w;
        *(float4*)(act + (size_t)r * IDIM + q * 4) = o;
    }
}

// --------------------------- combine ----------------------------------------
__global__ void combine_kernel(float* __restrict__ out)
{
    const int t = blockIdx.x;
    int pos[TOPK];
    #pragma unroll
    for (int k = 0; k < TOPK; ++k) pos[k] = g_pos_of_pair[t * TOPK + k];
    for (int q = threadIdx.x; q < HDIM / 4; q += blockDim.x) {
        float4 o = *(float4*)(out + (size_t)t * HDIM + q * 4);
        #pragma unroll
        for (int k = 0; k < TOPK; ++k) {
            float4 v = *(const float4*)(g_y + (size_t)pos[k] * HDIM + q * 4);
            o.x += v.x; o.y += v.y; o.z += v.z; o.w += v.w;
        }
        *(float4*)(out + (size_t)t * HDIM + q * 4) = o;
    }
}

// --------------------------- launch -----------------------------------------
extern "C" void kernel_launch(void* const* d_in, const int* in_sizes, int n_in,
                              void* d_out, int out_size)
{
    const float* hidden    = (const float*)d_in[0];
    const float* gate_w    = (const float*)d_in[1];
    const float* e_bias    = (const float*)d_in[2];
    const float* w_gate_up = (const float*)d_in[3];
    const float* w_down    = (const float*)d_in[4];
    const float* sh_gu     = (const float*)d_in[5];
    const float* sh_down   = (const float*)d_in[6];
    float* out             = (float*)d_out;

    void *p_gu, *p_act, *p_y, *p_gu_s, *p_act_s, *p_counts, *p_offsets,
         *p_stok, *p_sws;
    cudaGetSymbolAddress(&p_gu,     g_gu);
    cudaGetSymbolAddress(&p_act,    g_act);
    cudaGetSymbolAddress(&p_y,      g_y);
    cudaGetSymbolAddress(&p_gu_s,   g_gu_s);
    cudaGetSymbolAddress(&p_act_s,  g_act_s);
    cudaGetSymbolAddress(&p_counts, g_counts);
    cudaGetSymbolAddress(&p_offsets,g_offsets);
    cudaGetSymbolAddress(&p_stok,   g_sorted_token);
    cudaGetSymbolAddress(&p_sws,    g_sorted_ws);

    static bool attr_set = false;
    if (!attr_set) {
        cudaFuncSetAttribute(gemm_tf32_kernel,
                             cudaFuncAttributeMaxDynamicSharedMemorySize,
                             GEMM_SMEM_BYTES);
        attr_set = true;
    }

    // launch 0-2: router, count, scan
    router_kernel<<<TTOK, 32>>>(hidden, gate_w, e_bias);
    count_kernel<<<EXP, 256>>>();
    scan_kernel<<<1, 32>>>();

    // launch 3 (ncu profiles this): shared expert gate_up GEMM
    gemm_tf32_kernel<<<dim3(16, 2 * IDIM / BN, 1), 256, GEMM_SMEM_BYTES>>>(
        hidden, sh_gu, (float*)p_gu_s,
        TTOK, 2 * IDIM, HDIM,
        nullptr, nullptr, nullptr, nullptr, 0);

    // launch 4: place (completes the pair sort)
    place_kernel<<<EXP, 256>>>();

    // routed gate_up -> g_gu [6144, 2048]
    gemm_tf32_kernel<<<dim3(16, 2 * IDIM / BN, EXP), 256, GEMM_SMEM_BYTES>>>(
        hidden, w_gate_up, (float*)p_gu,
        0, 2 * IDIM, HDIM,
        (const int*)p_counts, (const int*)p_offsets, (const int*)p_stok,
        nullptr, (size_t)HDIM * 2 * IDIM);

    // routed silu*mul -> g_act
    silu_mul_kernel<<<6144, 256>>>((const float*)p_gu, (float*)p_act, PAIRS);

    // routed down, row-scaled by w*2.5 -> g_y
    gemm_tf32_kernel<<<dim3(16, HDIM / BN, EXP), 256, GEMM_SMEM_BYTES>>>(
        (const float*)p_act, w_down, (float*)p_y,
        0, HDIM, IDIM,
        (const int*)p_counts, (const int*)p_offsets, nullptr,
        (const float*)p_sws, (size_t)IDIM * HDIM);

    // shared expert: silu -> down (writes out directly)
    silu_mul_kernel<<<1024, 256>>>((const float*)p_gu_s, (float*)p_act_s, TTOK);
    gemm_tf32_kernel<<<dim3(16, HDIM / BN, 1), 256, GEMM_SMEM_BYTES>>>(
        (const float*)p_act_s, sh_down, out,
        TTOK, HDIM, IDIM,
        nullptr, nullptr, nullptr, nullptr, 0);

    // out += sum of each token's 6 scaled expert rows
    combine_kernel<<<TTOK, 256>>>(out);
}

// round 8
// speedup vs baseline: 1.1544x; 1.0745x over previous
#include <cuda_runtime.h>
#include <cstdint>
#include <cstdio>

// ---------------------------------------------------------------------------
// MegrezMoeMoE: T=1024 tokens, H=2048, E=32 experts, I=1024, TOPK=6,
// NGROUP=8, TOPKG=4, shared expert I=1024, SCALE=2.5
//
// GEMMs feed raw fp32 bit patterns to tf32 mma.sync (RZ mantissa truncation).
// The deterministic truncation bias is cancelled by CORR=1.0007045 applied in
// the GEMM epilogue (before any nonlinearity). Validated: rel_err 5.4e-4.
// ---------------------------------------------------------------------------

constexpr int TTOK  = 1024;
constexpr int HDIM  = 2048;
constexpr int EXP   = 32;
constexpr int IDIM  = 1024;
constexpr int TOPK  = 6;
constexpr int NGRP  = 8;
constexpr int TOPKG = 4;
constexpr int GSIZE = EXP / NGRP;      // 4
constexpr int PAIRS = TTOK * TOPK;     // 6144
constexpr float RSCALE = 2.5f;
constexpr float CORR  = 1.0007045f;    // tf32-truncation bias correction

// ------------------------- scratch (device globals) ------------------------
__device__ int   g_topk_id[PAIRS];
__device__ float g_topk_w[PAIRS];
__device__ int   g_counts[EXP];
__device__ int   g_offsets[EXP];
__device__ int   g_sorted_token[PAIRS];
__device__ float g_sorted_ws[PAIRS];        // topk weight * RSCALE
__device__ int   g_pos_of_pair[PAIRS];
__device__ float g_gu   [(size_t)PAIRS * 2 * IDIM];  // 48MB
__device__ float g_act  [(size_t)PAIRS * IDIM];      // 24MB
__device__ float g_y    [(size_t)PAIRS * HDIM];      // 48MB
__device__ float g_gu_s [(size_t)TTOK * 2 * IDIM];   // 8MB
__device__ float g_act_s[(size_t)TTOK * IDIM];       // 4MB

// ------------------------------ router -------------------------------------
__global__ void router_kernel(const float* __restrict__ hidden,
                              const float* __restrict__ gate_w,
                              const float* __restrict__ e_bias)
{
    int t = blockIdx.x;
    int lane = threadIdx.x;            // 32 threads, lane == expert
    const float* x = hidden + (size_t)t * HDIM;

    float logit = 0.f;
    #pragma unroll 8
    for (int h = 0; h < HDIM; ++h)
        logit += x[h] * gate_w[(size_t)h * EXP + lane];

    float s  = 1.f / (1.f + expf(-logit));
    float sc = s + e_bias[lane];

    __shared__ float sm_s[EXP];
    __shared__ float sm_sc[EXP];
    sm_s[lane]  = s;
    sm_sc[lane] = sc;
    __syncwarp();

    if (lane == 0) {
        float gs[NGRP];
        #pragma unroll
        for (int g = 0; g < NGRP; ++g) {
            float m1 = -1e30f, m2 = -1e30f;
            #pragma unroll
            for (int j = 0; j < GSIZE; ++j) {
                float v = sm_sc[g * GSIZE + j];
                if (v > m1) { m2 = m1; m1 = v; }
                else if (v > m2) { m2 = v; }
            }
            gs[g] = m1 + m2;
        }
        bool gsel[NGRP];
        #pragma unroll
        for (int g = 0; g < NGRP; ++g) gsel[g] = false;
        for (int it = 0; it < TOPKG; ++it) {
            int best = -1; float bv = -1e30f;
            for (int g = 0; g < NGRP; ++g)
                if (!gsel[g] && gs[g] > bv) { bv = gs[g]; best = g; }
            gsel[best] = true;
        }
        bool taken[EXP];
        #pragma unroll
        for (int e = 0; e < EXP; ++e) taken[e] = false;
        int ids[TOPK]; float ws[TOPK]; float wsum = 0.f;
        for (int it = 0; it < TOPK; ++it) {
            int best = -1; float bv = -1e30f;
            for (int e = 0; e < EXP; ++e) {
                if (!gsel[e >> 2] || taken[e]) continue;
                if (sm_sc[e] > bv) { bv = sm_sc[e]; best = e; }
            }
            taken[best] = true;
            ids[it] = best;
            ws[it]  = sm_s[best];
            wsum += ws[it];
        }
        float inv = 1.f / wsum;
        #pragma unroll
        for (int k = 0; k < TOPK; ++k) {
            g_topk_id[t * TOPK + k] = ids[k];
            g_topk_w [t * TOPK + k] = ws[k] * inv;
        }
    }
}

// ---------------------- deterministic counting sort -------------------------
__global__ void count_kernel()
{
    int e = blockIdx.x;
    int tid = threadIdx.x;
    int c = 0;
    for (int p = tid; p < PAIRS; p += blockDim.x)
        c += (g_topk_id[p] == e);
    __shared__ int red[256];
    red[tid] = c;
    __syncthreads();
    for (int s = 128; s > 0; s >>= 1) {
        if (tid < s) red[tid] += red[tid + s];
        __syncthreads();
    }
    if (tid == 0) g_counts[e] = red[0];
}

__global__ void scan_kernel()
{
    if (threadIdx.x == 0) {
        int acc = 0;
        for (int e = 0; e < EXP; ++e) { g_offsets[e] = acc; acc += g_counts[e]; }
    }
}

__global__ void place_kernel()
{
    int e = blockIdx.x;
    int tid = threadIdx.x;
    constexpr int CH = PAIRS / 256;    // 24
    int p0 = tid * CH;
    int c = 0;
    for (int i = 0; i < CH; ++i)
        c += (g_topk_id[p0 + i] == e);

    __shared__ int sc[256];
    sc[tid] = c;
    __syncthreads();
    for (int d = 1; d < 256; d <<= 1) {
        int v = (tid >= d) ? sc[tid - d] : 0;
        __syncthreads();
        sc[tid] += v;
        __syncthreads();
    }
    int pos = g_offsets[e] + sc[tid] - c;
    for (int i = 0; i < CH; ++i) {
        int p = p0 + i;
        if (g_topk_id[p] == e) {
            g_sorted_token[pos] = p / TOPK;
            g_sorted_ws[pos]    = g_topk_w[p] * RSCALE;
            g_pos_of_pair[p]    = pos;
            ++pos;
        }
    }
}

// --------------------------- tf32 GEMM core ---------------------------------
__device__ __forceinline__ void cp_async16(uint32_t dst, const void* src,
                                           int src_bytes)
{
    asm volatile("cp.async.cg.shared.global [%0], [%1], 16, %2;\n"
                 :: "r"(dst), "l"(src), "r"(src_bytes));
}
__device__ __forceinline__ void cp_commit()
{
    asm volatile("cp.async.commit_group;\n");
}
template <int N>
__device__ __forceinline__ void cp_wait()
{
    asm volatile("cp.async.wait_group %0;\n" :: "n"(N));
}

#define MMA_TF32(d, a, b)                                                  \
    asm volatile(                                                          \
        "mma.sync.aligned.m16n8k8.row.col.f32.tf32.tf32.f32 "              \
        "{%0,%1,%2,%3}, {%4,%5,%6,%7}, {%8,%9}, {%0,%1,%2,%3};\n"          \
        : "+f"(d[0]), "+f"(d[1]), "+f"(d[2]), "+f"(d[3])                   \
        : "r"(a[0]), "r"(a[1]), "r"(a[2]), "r"(a[3]), "r"(b[0]), "r"(b[1]))

// BM=64, BN=128, BK=16, 128 threads, 4 warps (2m x 2n), warp tile 32x64.
// 4-stage cp.async pipeline with fully-unrolled stage loop (compile-time
// buffer indices). 4 CTAs/SM -> 16 warps/SM from independent CTAs.
// Raw fp32 fed to tf32 MMA; truncation bias corrected by CORR in epilogue.
constexpr int STAGES = 4;
constexpr int BN = 128;
constexpr int A_FLOATS = 64 * 20;              // [m][k] stride 20
constexpr int B_FLOATS = 16 * 136;             // [k][n] stride 136
constexpr int STAGE_FLOATS = A_FLOATS + B_FLOATS;   // 3456
constexpr int GEMM_SMEM_BYTES = STAGES * STAGE_FLOATS * 4;  // 55296

__global__ __launch_bounds__(128, 4)
void gemm_tf32_kernel(const float* __restrict__ A,
                      const float* __restrict__ Bb,
                      float* __restrict__ C,
                      int M, int N, int K,
                      const int* __restrict__ counts,
                      const int* __restrict__ offsets,
                      const int* __restrict__ rowmap,
                      const float* __restrict__ rowscale,
                      size_t strideB)
{
    extern __shared__ float smem[];

    const int e = blockIdx.z;
    const int m_count = counts ? counts[e] : M;
    const int m0 = blockIdx.x * 64;
    if (m0 >= m_count) return;
    const int base = offsets ? offsets[e] : 0;
    const int n0 = blockIdx.y * BN;
    const float* B = Bb + (size_t)e * strideB;

    const int tid = threadIdx.x;

    // A loader: thread owns row ar, two k-quads aq,aq+1 (two 16B cp.async)
    const int ar = tid >> 1;            // 0..63
    const int aq = (tid & 1) * 2;       // 0 or 2
    const bool avalid = (m0 + ar) < m_count;
    const int grow_a = base + m0 + ar;
    const int arow = avalid ? (rowmap ? rowmap[grow_a] : grow_a) : 0;
    const float* Ap = A + (size_t)arow * K + aq * 4;
    const int abytes = avalid ? 16 : 0;

    // B loader: thread owns k-rows bkr+{0,4,8,12}, n-quad bnq (4 cp.async)
    const int bkr = tid >> 5;           // 0..3
    const int bnq = tid & 31;           // 0..31
    const float* Bp = B + (size_t)bkr * N + n0 + bnq * 4;

    const int wid = tid >> 5, lane = tid & 31;
    const int wm = (wid >> 1) * 32, wn = (wid & 1) * 64;
    const int gid = lane >> 2, tig = lane & 3;

    float acc[2][8][4];
    #pragma unroll
    for (int i = 0; i < 2; ++i)
        #pragma unroll
        for (int j = 0; j < 8; ++j)
            #pragma unroll
            for (int k = 0; k < 4; ++k) acc[i][j][k] = 0.f;

    const int nk = K / 16;   // 64 or 128; divisible by STAGES=4

    // per-thread smem byte offsets (stage 0); stage s adds s*STAGE_FLOATS*4
    const uint32_t smem_base = (uint32_t)__cvta_generic_to_shared(smem);
    const uint32_t a_off0 = smem_base + (ar * 20 + aq * 4) * 4;
    const uint32_t b_off0 = smem_base + (A_FLOATS + bkr * 136 + bnq * 4) * 4;
    constexpr uint32_t STAGE_BYTES = STAGE_FLOATS * 4;

    // prologue: stages 0..2 in flight
    #pragma unroll
    for (int s = 0; s < STAGES - 1; ++s) {
        const size_t ko = (size_t)s * 16;
        cp_async16(a_off0 + s * STAGE_BYTES, Ap + ko, abytes);
        cp_async16(a_off0 + s * STAGE_BYTES + 16, Ap + ko + 4, abytes);
        #pragma unroll
        for (int r = 0; r < 4; ++r)
            cp_async16(b_off0 + s * STAGE_BYTES + r * (4 * 136 * 4),
                       Bp + ko * N + (size_t)(r * 4) * N, 16);
        cp_commit();
    }

    for (int kb = 0; kb < nk; kb += STAGES) {
        #pragma unroll
        for (int s = 0; s < STAGES; ++s) {
            const int kt = kb + s;
            cp_wait<STAGES - 2>();   // stage kt arrived
            __syncthreads();

            // issue stage kt+3 into buffer (s+3)&3 (freed at iter kt-1)
            const int kf = kt + STAGES - 1;
            if (kf < nk) {
                const int fb = (s + STAGES - 1) % STAGES;   // compile-time
                const size_t ko = (size_t)kf * 16;
                cp_async16(a_off0 + fb * STAGE_BYTES, Ap + ko, abytes);
                cp_async16(a_off0 + fb * STAGE_BYTES + 16, Ap + ko + 4, abytes);
                #pragma unroll
                for (int r = 0; r < 4; ++r)
                    cp_async16(b_off0 + fb * STAGE_BYTES + r * (4 * 136 * 4),
                               Bp + ko * N + (size_t)(r * 4) * N, 16);
            }
            cp_commit();

            const uint32_t* As = (const uint32_t*)(smem + s * STAGE_FLOATS);
            const uint32_t* Bs = As + A_FLOATS;

            // compute on buffer s: raw fp32 bits straight into tf32 MMA
            #pragma unroll
            for (int ks = 0; ks < 2; ++ks) {
                const int kk = ks * 8;
                uint32_t a[2][4], b[8][2];
                #pragma unroll
                for (int mf = 0; mf < 2; ++mf) {
                    const int mr = wm + mf * 16 + gid;
                    a[mf][0] = As[(mr    ) * 20 + kk + tig];
                    a[mf][1] = As[(mr + 8) * 20 + kk + tig];
                    a[mf][2] = As[(mr    ) * 20 + kk + tig + 4];
                    a[mf][3] = As[(mr + 8) * 20 + kk + tig + 4];
                }
                #pragma unroll
                for (int nf = 0; nf < 8; ++nf) {
                    const int nc = wn + nf * 8 + gid;
                    b[nf][0] = Bs[(kk + tig    ) * 136 + nc];
                    b[nf][1] = Bs[(kk + tig + 4) * 136 + nc];
                }
                #pragma unroll
                for (int mf = 0; mf < 2; ++mf)
                    #pragma unroll
                    for (int nf = 0; nf < 8; ++nf)
                        MMA_TF32(acc[mf][nf], a[mf], b[nf]);
            }
        }
    }

    // epilogue (CORR cancels tf32-truncation bias; folded with rowscale)
    #pragma unroll
    for (int mf = 0; mf < 2; ++mf) {
        #pragma unroll
        for (int half = 0; half < 2; ++half) {
            const int rloc = wm + mf * 16 + gid + half * 8;
            if (m0 + rloc < m_count) {
                const int grow = base + m0 + rloc;
                const float scl = (rowscale ? rowscale[grow] : 1.f) * CORR;
                float* crow = C + (size_t)grow * N + n0 + wn;
                #pragma unroll
                for (int nf = 0; nf < 8; ++nf) {
                    float2 v;
                    v.x = acc[mf][nf][half * 2 + 0] * scl;
                    v.y = acc[mf][nf][half * 2 + 1] * scl;
                    *(float2*)(crow + nf * 8 + tig * 2) = v;
                }
            }
        }
    }
}

// --------------------------- silu * mul -------------------------------------
__global__ void silu_mul_kernel(const float* __restrict__ gu,
                                float* __restrict__ act, int rows)
{
    const int QI = IDIM / 4;
    int total = rows * QI;
    for (int idx = blockIdx.x * blockDim.x + threadIdx.x; idx < total;
         idx += gridDim.x * blockDim.x) {
        int r = idx / QI;
        int q = idx - r * QI;
        const float* row = gu + (size_t)r * 2 * IDIM;
        float4 g = *(const float4*)(row + q * 4);
        float4 u = *(const float4*)(row + IDIM + q * 4);
        float4 o;
        o.x = g.x / (1.f + __expf(-g.x)) * u.x;
        o.y = g.y / (1.f + __expf(-g.y)) * u.y;
        o.z = g.z / (1.f + __expf(-g.z)) * u.z;
        o.w = g.w / (1.f + __expf(-g.w)) * u.w;
        *(float4*)(act + (size_t)r * IDIM + q * 4) = o;
    }
}

// --------------------------- combine ----------------------------------------
__global__ void combine_kernel(float* __restrict__ out)
{
    const int t = blockIdx.x;
    int pos[TOPK];
    #pragma unroll
    for (int k = 0; k < TOPK; ++k) pos[k] = g_pos_of_pair[t * TOPK + k];
    for (int q = threadIdx.x; q < HDIM / 4; q += blockDim.x) {
        float4 o = *(float4*)(out + (size_t)t * HDIM + q * 4);
        #pragma unroll
        for (int k = 0; k < TOPK; ++k) {
            float4 v = *(const float4*)(g_y + (size_t)pos[k] * HDIM + q * 4);
            o.x += v.x; o.y += v.y; o.z += v.z; o.w += v.w;
        }
        *(float4*)(out + (size_t)t * HDIM + q * 4) = o;
    }
}

// --------------------------- launch -----------------------------------------
extern "C" void kernel_launch(void* const* d_in, const int* in_sizes, int n_in,
                              void* d_out, int out_size)
{
    const float* hidden    = (const float*)d_in[0];
    const float* gate_w    = (const float*)d_in[1];
    const float* e_bias    = (const float*)d_in[2];
    const float* w_gate_up = (const float*)d_in[3];
    const float* w_down    = (const float*)d_in[4];
    const float* sh_gu     = (const float*)d_in[5];
    const float* sh_down   = (const float*)d_in[6];
    float* out             = (float*)d_out;

    void *p_gu, *p_act, *p_y, *p_gu_s, *p_act_s, *p_counts, *p_offsets,
         *p_stok, *p_sws;
    cudaGetSymbolAddress(&p_gu,     g_gu);
    cudaGetSymbolAddress(&p_act,    g_act);
    cudaGetSymbolAddress(&p_y,      g_y);
    cudaGetSymbolAddress(&p_gu_s,   g_gu_s);
    cudaGetSymbolAddress(&p_act_s,  g_act_s);
    cudaGetSymbolAddress(&p_counts, g_counts);
    cudaGetSymbolAddress(&p_offsets,g_offsets);
    cudaGetSymbolAddress(&p_stok,   g_sorted_token);
    cudaGetSymbolAddress(&p_sws,    g_sorted_ws);

    static bool attr_set = false;
    if (!attr_set) {
        cudaFuncSetAttribute(gemm_tf32_kernel,
                             cudaFuncAttributeMaxDynamicSharedMemorySize,
                             GEMM_SMEM_BYTES);
        attr_set = true;
    }

    // launch 0-2: router, count, scan
    router_kernel<<<TTOK, 32>>>(hidden, gate_w, e_bias);
    count_kernel<<<EXP, 256>>>();
    scan_kernel<<<1, 32>>>();

    // launch 3 (ncu profiles this): shared expert gate_up GEMM
    gemm_tf32_kernel<<<dim3(16, 2 * IDIM / BN, 1), 128, GEMM_SMEM_BYTES>>>(
        hidden, sh_gu, (float*)p_gu_s,
        TTOK, 2 * IDIM, HDIM,
        nullptr, nullptr, nullptr, nullptr, 0);

    // launch 4: place (completes the pair sort)
    place_kernel<<<EXP, 256>>>();

    // routed gate_up -> g_gu [6144, 2048]
    gemm_tf32_kernel<<<dim3(16, 2 * IDIM / BN, EXP), 128, GEMM_SMEM_BYTES>>>(
        hidden, w_gate_up, (float*)p_gu,
        0, 2 * IDIM, HDIM,
        (const int*)p_counts, (const int*)p_offsets, (const int*)p_stok,
        nullptr, (size_t)HDIM * 2 * IDIM);

    // routed silu*mul -> g_act
    silu_mul_kernel<<<6144, 256>>>((const float*)p_gu, (float*)p_act, PAIRS);

    // routed down, row-scaled by w*2.5 -> g_y
    gemm_tf32_kernel<<<dim3(16, HDIM / BN, EXP), 128, GEMM_SMEM_BYTES>>>(
        (const float*)p_act, w_down, (float*)p_y,
        0, HDIM, IDIM,
        (const int*)p_counts, (const int*)p_offsets, nullptr,
        (const float*)p_sws, (size_t)IDIM * HDIM);

    // shared expert: silu -> down (writes out directly)
    silu_mul_kernel<<<1024, 256>>>((const float*)p_gu_s, (float*)p_act_s, TTOK);
    gemm_tf32_kernel<<<dim3(16, HDIM / BN, 1), 128, GEMM_SMEM_BYTES>>>(
        (const float*)p_act_s, sh_down, out,
        TTOK, HDIM, IDIM,
        nullptr, nullptr, nullptr, nullptr, 0);

    // out += sum of each token's 6 scaled expert rows
    combine_kernel<<<TTOK, 256>>>(out);
}